// round 6
// baseline (speedup 1.0000x reference)
#include <cuda_runtime.h>
#include <cuda_fp16.h>
#include <cstdint>
#define DI __device__ __forceinline__
namespace {
constexpr int INF=1024, OUTF=1024, KD=20480;
constexpr int KC=64, NCH=KD/KC;
constexpr int TST=128*KC*2;          // 16 KB per operand-stage
constexpr int SMEMSZ=4*2*TST;        // 128 KB

__device__ __align__(16) __half AH[(size_t)2048*KD];
__device__ __align__(16) __half WH[(size_t)OUTF*KD];

DI uint32_t swz(uint32_t o){return o^((o>>3)&0x70);}
DI uint32_t s2u(const void*p){uint32_t a;asm("{ .reg .u64 t; cvta.to.shared.u64 t, %1; cvt.u32.u64 %0, t; }":"=r"(a):"l"(p));return a;}
DI void cp16(uint32_t d,const void*s){asm volatile("cp.async.cg.shared.global [%0], [%1], 16;"::"r"(d),"l"(s):"memory");}
DI void cpc(){asm volatile("cp.async.commit_group;":::"memory");}
#define CPW(n) asm volatile("cp.async.wait_group %0;"::"n"(n):"memory")
DI void ldsm4(uint32_t*r,uint32_t a){asm volatile("ldmatrix.sync.aligned.m8n8.x4.shared.b16 {%0,%1,%2,%3}, [%4];":"=r"(r[0]),"=r"(r[1]),"=r"(r[2]),"=r"(r[3]):"r"(a));}
DI void mma(float*d,const uint32_t*a,const uint32_t*b){
  asm volatile("mma.sync.aligned.m16n8k16.row.col.f32.f16.f16.f32 {%0,%1,%2,%3},{%4,%5,%6,%7},{%8,%9},{%0,%1,%2,%3};"
  :"+f"(d[0]),"+f"(d[1]),"+f"(d[2]),"+f"(d[3])
  :"r"(a[0]),"r"(a[1]),"r"(a[2]),"r"(a[3]),"r"(b[0]),"r"(b[1]));}
DI float ex2f(float x){float r;asm("ex2.approx.ftz.f32 %0, %1;":"=f"(r):"f"(x));return r;}

__global__ void __launch_bounds__(256) kprep_basis(const float* __restrict__ X){
  int b=blockIdx.x; const float* xr=X+(size_t)b*INF;
  __half* dst=AH+(size_t)b*KD;
  for(int g=threadIdx.x; g<KD/8; g+=256){
    int j0=g*8; uint32_t w[4];
#pragma unroll
    for(int u=0;u<4;++u){
      float e[2];
#pragma unroll
      for(int v=0;v<2;++v){
        int j=j0+2*u+v; int i=j/20; int k=j-20*i;
        float t=fmaf(4.75f,__ldg(xr+i),9.5f-(float)k);
        e[v]=ex2f(-0.72134752044448170f*t*t);
      }
      __half2 h=__floats2half2_rn(e[0],e[1]);
      w[u]=*reinterpret_cast<uint32_t*>(&h);
    }
    uint4 o={w[0],w[1],w[2],w[3]};
    *reinterpret_cast<uint4*>(dst+j0)=o;
  }
}

__global__ void __launch_bounds__(256) kprep_w(const float* __restrict__ W){
  size_t g=(size_t)blockIdx.x*256+threadIdx.x;
  const float4* s=reinterpret_cast<const float4*>(W)+2*g;
  float4 p=__ldg(s), q=__ldg(s+1);
  __half2 h0=__floats2half2_rn(p.x,p.y),h1=__floats2half2_rn(p.z,p.w);
  __half2 h2=__floats2half2_rn(q.x,q.y),h3=__floats2half2_rn(q.z,q.w);
  uint4 o={*(uint32_t*)&h0,*(uint32_t*)&h1,*(uint32_t*)&h2,*(uint32_t*)&h3};
  reinterpret_cast<uint4*>(WH)[g]=o;
}

__global__ void __launch_bounds__(256,1) kgemm(float* __restrict__ out){
  extern __shared__ char sm[];
  const uint32_t sb=s2u(sm);
  const int tid=threadIdx.x, wid=tid>>5, ln=tid&31;
  const int m0=(blockIdx.x&15)*128, n0=(blockIdx.x>>4)*128;
  const __half* Ab=AH+(size_t)m0*KD;
  const __half* Bb=WH+(size_t)n0*KD;
  const int wm=wid>>1, wn=wid&1;
  float c[2][8][4];
#pragma unroll
  for(int i=0;i<2;++i)
#pragma unroll
    for(int j=0;j<8;++j)
#pragma unroll
      for(int k=0;k<4;++k) c[i][j][k]=0.f;

  auto load=[&](int ch){
    uint32_t s=sb+(uint32_t)(ch&3)*2u*TST;
#pragma unroll
    for(int q=0;q<4;++q){
      int seg=tid+q*256; int r=seg>>3,c16=seg&7;
      uint32_t off=swz((uint32_t)(r*128+c16*16));
      const size_t go=(size_t)r*KD+(size_t)ch*KC+c16*8;
      cp16(s+off, Ab+go);
      cp16(s+TST+off, Bb+go);
    }
    cpc();
  };
  load(0); load(1); load(2);

  for(int ch=0;ch<NCH;++ch){
    CPW(2); __syncthreads();
    const uint32_t sa=sb+(uint32_t)(ch&3)*2u*TST, sB=sa+TST;
#pragma unroll
    for(int ks=0;ks<4;++ks){
      const uint32_t colb=(uint32_t)((ks*16+((ln>>4)<<3))*2);
      uint32_t a[2][4], b[4][4];
#pragma unroll
      for(int mi=0;mi<2;++mi){
        int row=wm*32+mi*16+(ln&15);
        ldsm4(a[mi], sa+swz((uint32_t)row*128+colb));
      }
#pragma unroll
      for(int ni=0;ni<4;++ni){
        int row=wn*64+ni*16+(ln&7)+(ln&8);
        ldsm4(b[ni], sB+swz((uint32_t)row*128+colb));
      }
#pragma unroll
      for(int mi=0;mi<2;++mi)
#pragma unroll
        for(int ni=0;ni<4;++ni){
          uint32_t b0[2]={b[ni][0],b[ni][2]}, b1[2]={b[ni][1],b[ni][3]};
          mma(c[mi][2*ni],   a[mi], b0);
          mma(c[mi][2*ni+1], a[mi], b1);
        }
    }
    __syncthreads();
    if(ch+3<NCH) load(ch+3); else cpc();
  }

  float* dst=out+(size_t)m0*OUTF+n0;
#pragma unroll
  for(int mi=0;mi<2;++mi)
#pragma unroll
    for(int ni=0;ni<8;++ni){
      int r0=wm*32+mi*16+(ln>>2), col=wn*64+ni*8+(ln&3)*2;
      float2 v0; v0.x=c[mi][ni][0]; v0.y=c[mi][ni][1];
      float2 v1; v1.x=c[mi][ni][2]; v1.y=c[mi][ni][3];
      *reinterpret_cast<float2*>(dst+(size_t)r0*OUTF+col)=v0;
      *reinterpret_cast<float2*>(dst+(size_t)(r0+8)*OUTF+col)=v1;
    }
}
} // namespace

extern "C" void kernel_launch(void* const* d_in, const int* in_sizes, int n_in,
                              void* d_out, int out_size){
  (void)in_sizes;(void)n_in;(void)out_size;
  const float* X=(const float*)d_in[0];
  const float* W=(const float*)d_in[1];
  float* out=(float*)d_out;
  kprep_basis<<<2048,256>>>(X);
  kprep_w<<<(OUTF*(long)KD/8)/256,256>>>(W);
  cudaFuncSetAttribute(kgemm, cudaFuncAttributeMaxDynamicSharedMemorySize, SMEMSZ);
  kgemm<<<128,256,SMEMSZ>>>(out);
}

// round 9
// speedup vs baseline: 1.0518x; 1.0518x over previous
#include <cuda_runtime.h>
#include <cuda_fp16.h>
#include <cstdint>
#define DI __device__ __forceinline__
namespace {
constexpr int INF=1024, OUTF=1024, KD=20480;
constexpr int KC=64, NCH=KD/KC;      // 320 chunks
constexpr int TST=128*KC*2;          // 16 KB per operand-stage
constexpr int NSTG=6;
constexpr int SMEMSZ=NSTG*2*TST;     // 192 KB

__device__ __align__(16) __half AH[(size_t)2048*KD];
__device__ __align__(16) __half WH[(size_t)OUTF*KD];

DI uint32_t swz(uint32_t o){return o^((o>>3)&0x70);}
DI uint32_t s2u(const void*p){uint32_t a;asm("{ .reg .u64 t; cvta.to.shared.u64 t, %1; cvt.u32.u64 %0, t; }":"=r"(a):"l"(p));return a;}
DI void cp16(uint32_t d,const void*s){asm volatile("cp.async.cg.shared.global [%0], [%1], 16;"::"r"(d),"l"(s):"memory");}
DI void cpc(){asm volatile("cp.async.commit_group;":::"memory");}
#define CPW(n) asm volatile("cp.async.wait_group %0;"::"n"(n):"memory")
DI void ldsm4(uint32_t*r,uint32_t a){asm volatile("ldmatrix.sync.aligned.m8n8.x4.shared.b16 {%0,%1,%2,%3}, [%4];":"=r"(r[0]),"=r"(r[1]),"=r"(r[2]),"=r"(r[3]):"r"(a));}
DI void mma(float*d,const uint32_t*a,const uint32_t*b){
  asm volatile("mma.sync.aligned.m16n8k16.row.col.f32.f16.f16.f32 {%0,%1,%2,%3},{%4,%5,%6,%7},{%8,%9},{%0,%1,%2,%3};"
  :"+f"(d[0]),"+f"(d[1]),"+f"(d[2]),"+f"(d[3])
  :"r"(a[0]),"r"(a[1]),"r"(a[2]),"r"(a[3]),"r"(b[0]),"r"(b[1]));}
DI float ex2f(float x){float r;asm("ex2.approx.ftz.f32 %0, %1;":"=f"(r):"f"(x));return r;}

// merged prep: blocks [0,2048) build basis AH, blocks [2048,12288) convert W
__global__ void __launch_bounds__(256) kprep(const float* __restrict__ X,
                                            const float* __restrict__ W){
  if(blockIdx.x<2048){
    int b=blockIdx.x; const float* xr=X+(size_t)b*INF;
    __half* dst=AH+(size_t)b*KD;
    for(int g=threadIdx.x; g<KD/8; g+=256){
      int j0=g*8;
      int i0=j0/20, k0=j0-20*i0;                  // one div per 8 elems
      float xa=__ldg(xr+i0);
      float xb=(k0>12)?__ldg(xr+i0+1):xa;         // k0+7>=20 only if k0>=13
      uint32_t w[4];
#pragma unroll
      for(int u=0;u<4;++u){
        float e[2];
#pragma unroll
        for(int v=0;v<2;++v){
          int k=k0+2*u+v;
          bool hi=k>=20;
          float xv=hi?xb:xa;
          float kf=(float)(hi?k-20:k);
          float t=fmaf(4.75f,xv,9.5f-kf);
          e[v]=ex2f(-0.72134752044448170f*t*t);
        }
        __half2 h=__floats2half2_rn(e[0],e[1]);
        w[u]=*reinterpret_cast<uint32_t*>(&h);
      }
      uint4 o={w[0],w[1],w[2],w[3]};
      *reinterpret_cast<uint4*>(dst+j0)=o;
    }
  } else {
    size_t g=(size_t)(blockIdx.x-2048)*256+threadIdx.x;   // 10240*256 groups of 8
    const float4* s=reinterpret_cast<const float4*>(W)+2*g;
    float4 p=__ldg(s), q=__ldg(s+1);
    __half2 h0=__floats2half2_rn(p.x,p.y),h1=__floats2half2_rn(p.z,p.w);
    __half2 h2=__floats2half2_rn(q.x,q.y),h3=__floats2half2_rn(q.z,q.w);
    uint4 o={*(uint32_t*)&h0,*(uint32_t*)&h1,*(uint32_t*)&h2,*(uint32_t*)&h3};
    reinterpret_cast<uint4*>(WH)[g]=o;
  }
}

__global__ void __launch_bounds__(256,1) kgemm(float* __restrict__ out){
  extern __shared__ char sm[];
  const uint32_t sb=s2u(sm);
  const int tid=threadIdx.x, wid=tid>>5, ln=tid&31;
  const int m0=(blockIdx.x&15)*128, n0=(blockIdx.x>>4)*128;
  const __half* Ab=AH+(size_t)m0*KD;
  const __half* Bb=WH+(size_t)n0*KD;
  const int wm=wid>>1, wn=wid&1;
  float c[2][8][4];
#pragma unroll
  for(int i=0;i<2;++i)
#pragma unroll
    for(int j=0;j<8;++j)
#pragma unroll
      for(int k=0;k<4;++k) c[i][j][k]=0.f;

  int lst=0;  // load stage cursor
  auto load=[&](int ch){
    uint32_t s=sb+(uint32_t)lst*2u*TST;
    if(++lst==NSTG) lst=0;
#pragma unroll
    for(int q=0;q<4;++q){
      int seg=tid+q*256; int r=seg>>3,c16=seg&7;
      uint32_t off=swz((uint32_t)(r*128+c16*16));
      const size_t go=(size_t)r*KD+(size_t)ch*KC+c16*8;
      cp16(s+off, Ab+go);
      cp16(s+TST+off, Bb+go);
    }
    cpc();
  };
  load(0); load(1); load(2); load(3); load(4);   // 5 groups in flight

  int cst=0;  // consume stage cursor
  for(int ch=0;ch<NCH;++ch){
    CPW(4);
    __syncthreads();            // single barrier per chunk
    if(ch+5<NCH) load(ch+5); else cpc();   // issue next load FIRST (overlap)
    const uint32_t sa=sb+(uint32_t)cst*2u*TST, sB=sa+TST;
    if(++cst==NSTG) cst=0;
#pragma unroll
    for(int ks=0;ks<4;++ks){
      const uint32_t colb=(uint32_t)((ks*16+((ln>>4)<<3))*2);
      uint32_t a[2][4], b[4][4];
#pragma unroll
      for(int mi=0;mi<2;++mi){
        int row=wm*32+mi*16+(ln&15);
        ldsm4(a[mi], sa+swz((uint32_t)row*128+colb));
      }
#pragma unroll
      for(int ni=0;ni<4;++ni){
        int row=wn*64+ni*16+(ln&7)+(ln&8);
        ldsm4(b[ni], sB+swz((uint32_t)row*128+colb));
      }
#pragma unroll
      for(int mi=0;mi<2;++mi)
#pragma unroll
        for(int ni=0;ni<4;++ni){
          uint32_t b0[2]={b[ni][0],b[ni][2]}, b1[2]={b[ni][1],b[ni][3]};
          mma(c[mi][2*ni],   a[mi], b0);
          mma(c[mi][2*ni+1], a[mi], b1);
        }
    }
  }

  float* dst=out+(size_t)m0*OUTF+n0;
#pragma unroll
  for(int mi=0;mi<2;++mi)
#pragma unroll
    for(int ni=0;ni<8;++ni){
      int r0=wm*32+mi*16+(ln>>2), col=wn*64+ni*8+(ln&3)*2;
      float2 v0; v0.x=c[mi][ni][0]; v0.y=c[mi][ni][1];
      float2 v1; v1.x=c[mi][ni][2]; v1.y=c[mi][ni][3];
      *reinterpret_cast<float2*>(dst+(size_t)r0*OUTF+col)=v0;
      *reinterpret_cast<float2*>(dst+(size_t)(r0+8)*OUTF+col)=v1;
    }
}
} // namespace

extern "C" void kernel_launch(void* const* d_in, const int* in_sizes, int n_in,
                              void* d_out, int out_size){
  (void)in_sizes;(void)n_in;(void)out_size;
  const float* X=(const float*)d_in[0];
  const float* W=(const float*)d_in[1];
  float* out=(float*)d_out;
  kprep<<<12288,256>>>(X,W);
  cudaFuncSetAttribute(kgemm, cudaFuncAttributeMaxDynamicSharedMemorySize, SMEMSZ);
  kgemm<<<128,256,SMEMSZ>>>(out);
}

// round 10
// speedup vs baseline: 1.0940x; 1.0401x over previous
#include <cuda_runtime.h>
#include <cuda_fp16.h>
#include <cstdint>
#define DI __device__ __forceinline__
namespace {
constexpr int INF=1024, OUTF=1024, KD=20480;
constexpr int KC=64, NCH=KD/KC;      // 320 chunks
constexpr int TST=128*KC*2;          // 16 KB per operand-stage
constexpr int NSTG=6;
constexpr int SMEMSZ=NSTG*2*TST;     // 192 KB
constexpr int NTHR=512;              // 16 warps: 4Mx4N warp grid

__device__ __align__(16) __half AH[(size_t)2048*KD];
__device__ __align__(16) __half WH[(size_t)OUTF*KD];

DI uint32_t swz(uint32_t o){return o^((o>>3)&0x70);}
DI uint32_t s2u(const void*p){uint32_t a;asm("{ .reg .u64 t; cvta.to.shared.u64 t, %1; cvt.u32.u64 %0, t; }":"=r"(a):"l"(p));return a;}
DI void cp16(uint32_t d,const void*s){asm volatile("cp.async.cg.shared.global [%0], [%1], 16;"::"r"(d),"l"(s):"memory");}
DI void cpc(){asm volatile("cp.async.commit_group;":::"memory");}
#define CPW(n) asm volatile("cp.async.wait_group %0;"::"n"(n):"memory")
DI void ldsm4(uint32_t*r,uint32_t a){asm volatile("ldmatrix.sync.aligned.m8n8.x4.shared.b16 {%0,%1,%2,%3}, [%4];":"=r"(r[0]),"=r"(r[1]),"=r"(r[2]),"=r"(r[3]):"r"(a));}
DI void mma(float*d,const uint32_t*a,const uint32_t*b){
  asm volatile("mma.sync.aligned.m16n8k16.row.col.f32.f16.f16.f32 {%0,%1,%2,%3},{%4,%5,%6,%7},{%8,%9},{%0,%1,%2,%3};"
  :"+f"(d[0]),"+f"(d[1]),"+f"(d[2]),"+f"(d[3])
  :"r"(a[0]),"r"(a[1]),"r"(a[2]),"r"(a[3]),"r"(b[0]),"r"(b[1]));}
DI float ex2f(float x){float r;asm("ex2.approx.ftz.f32 %0, %1;":"=f"(r):"f"(x));return r;}

// merged prep: blocks [0,2048) build basis AH, blocks [2048,12288) convert W
__global__ void __launch_bounds__(256) kprep(const float* __restrict__ X,
                                            const float* __restrict__ W){
  if(blockIdx.x<2048){
    int b=blockIdx.x; const float* xr=X+(size_t)b*INF;
    __half* dst=AH+(size_t)b*KD;
    for(int g=threadIdx.x; g<KD/8; g+=256){
      int j0=g*8;
      int i0=j0/20, k0=j0-20*i0;
      float xa=__ldg(xr+i0);
      float xb=(k0>12)?__ldg(xr+i0+1):xa;
      uint32_t w[4];
#pragma unroll
      for(int u=0;u<4;++u){
        float e[2];
#pragma unroll
        for(int v=0;v<2;++v){
          int k=k0+2*u+v;
          bool hi=k>=20;
          float xv=hi?xb:xa;
          float kf=(float)(hi?k-20:k);
          float t=fmaf(4.75f,xv,9.5f-kf);
          e[v]=ex2f(-0.72134752044448170f*t*t);
        }
        __half2 h=__floats2half2_rn(e[0],e[1]);
        w[u]=*reinterpret_cast<uint32_t*>(&h);
      }
      uint4 o={w[0],w[1],w[2],w[3]};
      *reinterpret_cast<uint4*>(dst+j0)=o;
    }
  } else {
    size_t g=(size_t)(blockIdx.x-2048)*256+threadIdx.x;
    const float4* s=reinterpret_cast<const float4*>(W)+2*g;
    float4 p=__ldg(s), q=__ldg(s+1);
    __half2 h0=__floats2half2_rn(p.x,p.y),h1=__floats2half2_rn(p.z,p.w);
    __half2 h2=__floats2half2_rn(q.x,q.y),h3=__floats2half2_rn(q.z,q.w);
    uint4 o={*(uint32_t*)&h0,*(uint32_t*)&h1,*(uint32_t*)&h2,*(uint32_t*)&h3};
    reinterpret_cast<uint4*>(WH)[g]=o;
  }
}

__global__ void __launch_bounds__(NTHR,1) kgemm(float* __restrict__ out){
  extern __shared__ char sm[];
  const uint32_t sb=s2u(sm);
  const int tid=threadIdx.x, wid=tid>>5, ln=tid&31;
  const int m0=(blockIdx.x&15)*128, n0=(blockIdx.x>>4)*128;
  const __half* Ab=AH+(size_t)m0*KD;
  const __half* Bb=WH+(size_t)n0*KD;
  const int wm=wid>>2, wn=wid&3;          // 4x4 warp grid, 32x32 warp tile
  float c[2][4][4];
#pragma unroll
  for(int i=0;i<2;++i)
#pragma unroll
    for(int j=0;j<4;++j)
#pragma unroll
      for(int k=0;k<4;++k) c[i][j][k]=0.f;

  int lst=0;
  auto load=[&](int ch){
    uint32_t s=sb+(uint32_t)lst*2u*TST;
    if(++lst==NSTG) lst=0;
#pragma unroll
    for(int q=0;q<2;++q){
      int seg=tid+q*NTHR; int r=seg>>3,c16=seg&7;
      uint32_t off=swz((uint32_t)(r*128+c16*16));
      const size_t go=(size_t)r*KD+(size_t)ch*KC+c16*8;
      cp16(s+off, Ab+go);
      cp16(s+TST+off, Bb+go);
    }
    cpc();
  };
  load(0); load(1); load(2); load(3); load(4);

  int cst=0;
  for(int ch=0;ch<NCH;++ch){
    CPW(4);
    __syncthreads();
    if(ch+5<NCH) load(ch+5); else cpc();
    const uint32_t sa=sb+(uint32_t)cst*2u*TST, sB=sa+TST;
    if(++cst==NSTG) cst=0;
#pragma unroll
    for(int ks=0;ks<4;++ks){
      const uint32_t colb=(uint32_t)((ks*16+((ln>>4)<<3))*2);
      uint32_t a[2][4], b[2][4];
#pragma unroll
      for(int mi=0;mi<2;++mi){
        int row=wm*32+mi*16+(ln&15);
        ldsm4(a[mi], sa+swz((uint32_t)row*128+colb));
      }
#pragma unroll
      for(int ni=0;ni<2;++ni){
        int row=wn*32+ni*16+(ln&7)+(ln&8);
        ldsm4(b[ni], sB+swz((uint32_t)row*128+colb));
      }
#pragma unroll
      for(int mi=0;mi<2;++mi)
#pragma unroll
        for(int ni=0;ni<2;++ni){
          uint32_t b0[2]={b[ni][0],b[ni][2]}, b1[2]={b[ni][1],b[ni][3]};
          mma(c[mi][2*ni],   a[mi], b0);
          mma(c[mi][2*ni+1], a[mi], b1);
        }
    }
  }

  float* dst=out+(size_t)m0*OUTF+n0;
#pragma unroll
  for(int mi=0;mi<2;++mi)
#pragma unroll
    for(int j=0;j<4;++j){
      int r0=wm*32+mi*16+(ln>>2);
      int col=wn*32+(j>>1)*16+(j&1)*8+(ln&3)*2;
      float2 v0; v0.x=c[mi][j][0]; v0.y=c[mi][j][1];
      float2 v1; v1.x=c[mi][j][2]; v1.y=c[mi][j][3];
      *reinterpret_cast<float2*>(dst+(size_t)r0*OUTF+col)=v0;
      *reinterpret_cast<float2*>(dst+(size_t)(r0+8)*OUTF+col)=v1;
    }
}
} // namespace

extern "C" void kernel_launch(void* const* d_in, const int* in_sizes, int n_in,
                              void* d_out, int out_size){
  (void)in_sizes;(void)n_in;(void)out_size;
  const float* X=(const float*)d_in[0];
  const float* W=(const float*)d_in[1];
  float* out=(float*)d_out;
  kprep<<<12288,256>>>(X,W);
  cudaFuncSetAttribute(kgemm, cudaFuncAttributeMaxDynamicSharedMemorySize, SMEMSZ);
  kgemm<<<128,NTHR,SMEMSZ>>>(out);
}